// round 7
// baseline (speedup 1.0000x reference)
#include <cuda_runtime.h>
#include <cstdint>

// CoverageAttention GB300 — R6: 64x64 warp-tile tf32 GEMM (smem-byte economy),
// 512-thread attention, tf32 pre-rounding to kill hot-loop cvts.
// B=8, Tq=Tk=1024, d_model=1024, H=16, hd=64, SCALE=8.

#define NB   8
#define NH   16
#define NT   1024
#define NDM  1024
#define NHD  64

__device__ float g_Q[NB * NH * NT * NHD];
__device__ float g_K[NB * NH * NT * NHD];
__device__ float g_V[NB * NH * NT * NHD];
__device__ float g_O[NB * NT * NDM];
__device__ float g_covacc[NB * NT];

__global__ void zero_covacc_kernel() {
    int i = blockIdx.x * 256 + threadIdx.x;
    if (i < NB * NT) g_covacc[i] = 0.0f;
}

__device__ __forceinline__ uint32_t smem_u32(const void* p) {
    uint32_t a;
    asm("{ .reg .u64 t; cvta.to.shared.u64 t, %1; cvt.u32.u64 %0, t; }" : "=r"(a) : "l"(p));
    return a;
}
__device__ __forceinline__ uint32_t f2tf32(float x) {
    uint32_t r;
    asm("cvt.rna.tf32.f32 %0, %1;" : "=r"(r) : "f"(x));
    return r;
}
__device__ __forceinline__ float roundtf(float x) {
    return __uint_as_float(f2tf32(x));
}
__device__ __forceinline__ void mma_tf32(float c[4],
                                         uint32_t a0, uint32_t a1, uint32_t a2, uint32_t a3,
                                         uint32_t b0, uint32_t b1) {
    asm volatile(
        "mma.sync.aligned.m16n8k8.row.col.f32.tf32.tf32.f32 "
        "{%0,%1,%2,%3}, {%4,%5,%6,%7}, {%8,%9}, {%0,%1,%2,%3};"
        : "+f"(c[0]), "+f"(c[1]), "+f"(c[2]), "+f"(c[3])
        : "r"(a0), "r"(a1), "r"(a2), "r"(a3), "r"(b0), "r"(b1));
}

#define CP16(dst, src) \
    asm volatile("cp.async.cg.shared.global [%0], [%1], 16;" :: "r"(dst), "l"(src) : "memory")
#define CPC() asm volatile("cp.async.commit_group;" ::: "memory")
#define CPW(n) asm volatile("cp.async.wait_group %0;" :: "n"(n) : "memory")

// ================= tf32 GEMM =================
// C[m,n] = A[m,:]·W[n,:] + bias[n]; M=8192, N=1024, K=1024.
// CTA 128x256, BK=16, 256 thr = 8 warps (2x4), warp 64x64 = 4x8 m16n8k8.
// smem (dynamic, words): As[2][128][20] @0, Ws[2][256][20] @5120. 61440 B.
#define GS_W 5120
#define G_SMEM_BYTES 61440

template <int DST>
__global__ __launch_bounds__(256) void gemm_mma(
    const float* __restrict__ A, const float* __restrict__ W,
    const float* __restrict__ bias, float* __restrict__ Cout)
{
    extern __shared__ uint32_t gsm[];
    uint32_t (*As)[128][20] = (uint32_t(*)[128][20])(gsm);
    uint32_t (*Ws)[256][20] = (uint32_t(*)[256][20])(gsm + GS_W);

    int tid = threadIdx.x;
    int lane = tid & 31;
    int wid = tid >> 5;
    int warp_m = wid & 1;        // 2 along M (64 rows each)
    int warp_n = wid >> 1;       // 4 along N (64 cols each)
    int g = lane >> 2;
    int t = lane & 3;

    int bm = blockIdx.y * 128;
    int bn = blockIdx.x * 256;

    const float* Ap = (DST == 3) ? (const float*)g_O : A;

    int lr_a = tid >> 1;             // 0..127
    int ka   = (tid & 1) * 8;        // 0/8
    const float* aP = Ap + (size_t)(bm + lr_a) * NDM + ka;
    const float* wP = W  + (size_t)(bn + tid) * NDM;   // 256 rows, 1 per thread

    float c[4][8][4];
#pragma unroll
    for (int mi = 0; mi < 4; mi++)
#pragma unroll
        for (int ni = 0; ni < 8; ni++)
#pragma unroll
            for (int e = 0; e < 4; e++) c[mi][ni][e] = 0.0f;

    float4 ar0 = *(const float4*)(aP + 0);
    float4 ar1 = *(const float4*)(aP + 4);
    float4 wr0 = *(const float4*)(wP + 0);
    float4 wr1 = *(const float4*)(wP + 4);
    float4 wr2 = *(const float4*)(wP + 8);
    float4 wr3 = *(const float4*)(wP + 12);

    // store slab 0
    {
        uint4 q0 = {f2tf32(ar0.x), f2tf32(ar0.y), f2tf32(ar0.z), f2tf32(ar0.w)};
        uint4 q1 = {f2tf32(ar1.x), f2tf32(ar1.y), f2tf32(ar1.z), f2tf32(ar1.w)};
        *(uint4*)&As[0][lr_a][ka]     = q0;
        *(uint4*)&As[0][lr_a][ka + 4] = q1;
        uint4 p0 = {f2tf32(wr0.x), f2tf32(wr0.y), f2tf32(wr0.z), f2tf32(wr0.w)};
        uint4 p1 = {f2tf32(wr1.x), f2tf32(wr1.y), f2tf32(wr1.z), f2tf32(wr1.w)};
        uint4 p2 = {f2tf32(wr2.x), f2tf32(wr2.y), f2tf32(wr2.z), f2tf32(wr2.w)};
        uint4 p3 = {f2tf32(wr3.x), f2tf32(wr3.y), f2tf32(wr3.z), f2tf32(wr3.w)};
        *(uint4*)&Ws[0][tid][0]  = p0;
        *(uint4*)&Ws[0][tid][4]  = p1;
        *(uint4*)&Ws[0][tid][8]  = p2;
        *(uint4*)&Ws[0][tid][12] = p3;
    }
    __syncthreads();

    for (int kt = 0; kt < 64; kt++) {
        int cur = kt & 1;
        if (kt < 63) {
            const float* aN = aP + (kt + 1) * 16;
            const float* wN = wP + (kt + 1) * 16;
            ar0 = *(const float4*)(aN + 0);
            ar1 = *(const float4*)(aN + 4);
            wr0 = *(const float4*)(wN + 0);
            wr1 = *(const float4*)(wN + 4);
            wr2 = *(const float4*)(wN + 8);
            wr3 = *(const float4*)(wN + 12);
        }

#pragma unroll
        for (int kk = 0; kk < 16; kk += 8) {
            uint32_t af[4][4];
#pragma unroll
            for (int mi = 0; mi < 4; mi++) {
                int r0 = warp_m * 64 + mi * 16 + g;
                af[mi][0] = As[cur][r0][kk + t];
                af[mi][1] = As[cur][r0 + 8][kk + t];
                af[mi][2] = As[cur][r0][kk + t + 4];
                af[mi][3] = As[cur][r0 + 8][kk + t + 4];
            }
#pragma unroll
            for (int ni = 0; ni < 8; ni++) {
                int c0 = warp_n * 64 + ni * 8 + g;
                uint32_t b0 = Ws[cur][c0][kk + t];
                uint32_t b1 = Ws[cur][c0][kk + t + 4];
#pragma unroll
                for (int mi = 0; mi < 4; mi++)
                    mma_tf32(c[mi][ni], af[mi][0], af[mi][1], af[mi][2], af[mi][3], b0, b1);
            }
        }

        if (kt < 63) {
            int nxt = cur ^ 1;
            uint4 q0 = {f2tf32(ar0.x), f2tf32(ar0.y), f2tf32(ar0.z), f2tf32(ar0.w)};
            uint4 q1 = {f2tf32(ar1.x), f2tf32(ar1.y), f2tf32(ar1.z), f2tf32(ar1.w)};
            *(uint4*)&As[nxt][lr_a][ka]     = q0;
            *(uint4*)&As[nxt][lr_a][ka + 4] = q1;
            uint4 p0 = {f2tf32(wr0.x), f2tf32(wr0.y), f2tf32(wr0.z), f2tf32(wr0.w)};
            uint4 p1 = {f2tf32(wr1.x), f2tf32(wr1.y), f2tf32(wr1.z), f2tf32(wr1.w)};
            uint4 p2 = {f2tf32(wr2.x), f2tf32(wr2.y), f2tf32(wr2.z), f2tf32(wr2.w)};
            uint4 p3 = {f2tf32(wr3.x), f2tf32(wr3.y), f2tf32(wr3.z), f2tf32(wr3.w)};
            *(uint4*)&Ws[nxt][tid][0]  = p0;
            *(uint4*)&Ws[nxt][tid][4]  = p1;
            *(uint4*)&Ws[nxt][tid][8]  = p2;
            *(uint4*)&Ws[nxt][tid][12] = p3;
            __syncthreads();
        }
    }

    // epilogue (DST<3: round outputs to tf32 so consumers skip cvt)
#pragma unroll
    for (int mi = 0; mi < 4; mi++) {
#pragma unroll
        for (int ni = 0; ni < 8; ni++) {
            int n0 = bn + warp_n * 64 + ni * 8 + t * 2;
            float b0v = __ldg(bias + n0);
            float b1v = __ldg(bias + n0 + 1);
#pragma unroll
            for (int rh = 0; rh < 2; rh++) {
                int m = bm + warp_m * 64 + mi * 16 + g + rh * 8;
                float v0 = c[mi][ni][rh * 2 + 0] + b0v;
                float v1 = c[mi][ni][rh * 2 + 1] + b1v;
                int bb = m >> 10, tok = m & 1023;
                if (DST == 3) {
                    Cout[(size_t)m * NDM + n0] = v0;
                    Cout[(size_t)m * NDM + n0 + 1] = v1;
                } else {
                    size_t base = (((size_t)(bb * NH + (n0 >> 6))) * NT + tok) * NHD + (n0 & 63);
                    float* dst = (DST == 0) ? g_Q : (DST == 1) ? g_K : g_V;
                    dst[base] = roundtf(v0); dst[base + 1] = roundtf(v1);
                }
            }
        }
    }
}

// ================= attention (mma.sync, 512 threads) =================
#define SROW    1033
#define OFF_S   0                    // 32 x 1033
#define OFF_KV0 33056                // 128 x 68 (buffer 0)
#define OFF_KV1 41760                // 128 x 68 (buffer 1)
#define OFF_QS  50464                // 32 x 68 Q staging
#define OFF_C   52640                // 1024 coverage bias
#define OFF_R   53664                // 32 reciprocals
#define A_SMEM_FLOATS 53696
#define A_SMEM_BYTES  (A_SMEM_FLOATS * 4)   // 214784

__global__ __launch_bounds__(512) void attn_mma(
    const float* __restrict__ coverage, const float* __restrict__ Wcov)
{
    extern __shared__ float sm[];
    uint32_t sb = smem_u32(sm);
    int tid = threadIdx.x;
    int lane = tid & 31, wid = tid >> 5;
    int g = lane >> 2, t = lane & 3;
    int bh = blockIdx.y, b = bh >> 4, h = bh & 15;
    int q0 = blockIdx.x * 32;
    float wcov = Wcov[h];

    const float* Qb = g_Q + (size_t)bh * NT * NHD + (size_t)q0 * NHD;
    const float* Kb = g_K + (size_t)bh * NT * NHD;
    const float* Vb = g_V + (size_t)bh * NT * NHD;

    // ---- prologue: Q + cov + K0, K1 ----
    {
        int q = tid >> 4, c4 = tid & 15;
        CP16(sb + (OFF_QS + q * 68 + c4 * 4) * 4, Qb + q * 64 + c4 * 4);
    }
    if (tid < 256) CP16(sb + (OFF_C + tid * 4) * 4, coverage + b * NT + tid * 4);
#pragma unroll
    for (int i = 0; i < 4; i++) {
        int id = tid + 512 * i;
        int tok = id >> 4, c4 = id & 15;
        CP16(sb + (OFF_KV0 + tok * 68 + c4 * 4) * 4, Kb + tok * 64 + c4 * 4);
    }
    CPC();
#pragma unroll
    for (int i = 0; i < 4; i++) {
        int id = tid + 512 * i;
        int tok = id >> 4, c4 = id & 15;
        CP16(sb + (OFF_KV1 + tok * 68 + c4 * 4) * 4, Kb + (128 + tok) * 64 + c4 * 4);
    }
    CPC();
    CPW(1);
    __syncthreads();

    for (int i = tid; i < NT; i += 512) sm[OFF_C + i] *= wcov;

    // Q fragments (values pre-rounded to tf32 by producer — raw bits)
    uint32_t qf[2][8][4];
#pragma unroll
    for (int mi = 0; mi < 2; mi++)
#pragma unroll
        for (int kk = 0; kk < 8; kk++) {
            int base = OFF_QS + (mi * 16 + g) * 68 + kk * 8 + t;
            qf[mi][kk][0] = __float_as_uint(sm[base]);
            qf[mi][kk][1] = __float_as_uint(sm[base + 8 * 68]);
            qf[mi][kk][2] = __float_as_uint(sm[base + 4]);
            qf[mi][kk][3] = __float_as_uint(sm[base + 8 * 68 + 4]);
        }
    __syncthreads();

    // -------- phase 1: S = QK^T/8 + cov; each warp owns 8 tokens --------
    int tokb = wid * 8;
    for (int kt = 0; kt < 8; kt++) {
        if (kt) {
            if (kt < 7) { CPW(1); } else { CPW(0); }
            __syncthreads();
        }
        const float* Ks = sm + ((kt & 1) ? OFF_KV1 : OFF_KV0);
        const float* kr = Ks + (tokb + g) * 68 + t;
        float s0[4] = {0, 0, 0, 0}, s1[4] = {0, 0, 0, 0};
#pragma unroll
        for (int kk = 0; kk < 8; kk++) {
            uint32_t b0 = __float_as_uint(kr[kk * 8]);
            uint32_t b1 = __float_as_uint(kr[kk * 8 + 4]);
            mma_tf32(s0, qf[0][kk][0], qf[0][kk][1], qf[0][kk][2], qf[0][kk][3], b0, b1);
            mma_tf32(s1, qf[1][kk][0], qf[1][kk][1], qf[1][kk][2], qf[1][kk][3], b0, b1);
        }
        int kgl = kt * 128 + tokb + 2 * t;
        float cv0 = sm[OFF_C + kgl], cv1 = sm[OFF_C + kgl + 1];
        sm[OFF_S + g * SROW + kgl]            = s0[0] * 0.125f + cv0;
        sm[OFF_S + g * SROW + kgl + 1]        = s0[1] * 0.125f + cv1;
        sm[OFF_S + (g + 8) * SROW + kgl]      = s0[2] * 0.125f + cv0;
        sm[OFF_S + (g + 8) * SROW + kgl + 1]  = s0[3] * 0.125f + cv1;
        sm[OFF_S + (g + 16) * SROW + kgl]     = s1[0] * 0.125f + cv0;
        sm[OFF_S + (g + 16) * SROW + kgl + 1] = s1[1] * 0.125f + cv1;
        sm[OFF_S + (g + 24) * SROW + kgl]     = s1[2] * 0.125f + cv0;
        sm[OFF_S + (g + 24) * SROW + kgl + 1] = s1[3] * 0.125f + cv1;
        __syncthreads();
        if (kt < 6) {
            uint32_t dof = (kt & 1) ? OFF_KV1 : OFF_KV0;
#pragma unroll
            for (int i = 0; i < 4; i++) {
                int id = tid + 512 * i;
                int tok = id >> 4, c4 = id & 15;
                CP16(sb + (dof + tok * 68 + c4 * 4) * 4,
                     Kb + ((kt + 2) * 128 + tok) * 64 + c4 * 4);
            }
            CPC();
        }
    }

    // issue V tiles 0,1 (hidden under softmax)
#pragma unroll
    for (int i = 0; i < 4; i++) {
        int id = tid + 512 * i;
        int tok = id >> 4, c4 = id & 15;
        CP16(sb + (OFF_KV0 + tok * 68 + c4 * 4) * 4, Vb + tok * 64 + c4 * 4);
    }
    CPC();
#pragma unroll
    for (int i = 0; i < 4; i++) {
        int id = tid + 512 * i;
        int tok = id >> 4, c4 = id & 15;
        CP16(sb + (OFF_KV1 + tok * 68 + c4 * 4) * 4, Vb + (128 + tok) * 64 + c4 * 4);
    }
    CPC();

    // -------- phase 2: softmax --------
    for (int q = wid; q < 32; q += 16) {
        float* row = &sm[OFF_S + q * SROW];
        float m = -1e30f;
        for (int k = lane; k < NT; k += 32) m = fmaxf(m, row[k]);
#pragma unroll
        for (int o = 16; o > 0; o >>= 1) m = fmaxf(m, __shfl_xor_sync(0xffffffff, m, o));
        float l = 0.0f;
        for (int k = lane; k < NT; k += 32) {
            float e = __expf(row[k] - m);
            row[k] = e;
            l += e;
        }
#pragma unroll
        for (int o = 16; o > 0; o >>= 1) l += __shfl_xor_sync(0xffffffff, l, o);
        if (lane == 0) sm[OFF_R + q] = 1.0f / l;
    }
    __syncthreads();

    // -------- phase 3: coverage column sums --------
    for (int k = tid; k < NT; k += 512) {
        float s = 0.0f;
#pragma unroll 8
        for (int q = 0; q < 32; q++)
            s += sm[OFF_S + q * SROW + k] * sm[OFF_R + q];
        atomicAdd(&g_covacc[b * NT + k], s);
    }

    // -------- phase 4: O = P @ V; warps = kp(4) x mh(2) x nh(2) --------
    int kp = wid & 3, mh = (wid >> 2) & 1, nh = wid >> 3;
    float oa[4][4];
#pragma unroll
    for (int nj = 0; nj < 4; nj++)
#pragma unroll
        for (int e = 0; e < 4; e++) oa[nj][e] = 0.0f;

    for (int kt = 0; kt < 8; kt++) {
        if (kt < 7) { CPW(1); } else { CPW(0); }
        __syncthreads();
        const float* Vs = sm + ((kt & 1) ? OFF_KV1 : OFF_KV0);
#pragma unroll
        for (int s = 0; s < 4; s++) {
            int kb = (s * 4 + kp) * 8;
            int ar = OFF_S + (mh * 16 + g) * SROW + kt * 128 + kb + t;
            uint32_t a0 = f2tf32(sm[ar]);
            uint32_t a1 = f2tf32(sm[ar + 8 * SROW]);
            uint32_t a2 = f2tf32(sm[ar + 4]);
            uint32_t a3 = f2tf32(sm[ar + 8 * SROW + 4]);
#pragma unroll
            for (int nj = 0; nj < 4; nj++) {
                int d0 = nh * 32 + nj * 8 + g;
                uint32_t b0 = __float_as_uint(Vs[(kb + t) * 68 + d0]);
                uint32_t b1 = __float_as_uint(Vs[(kb + t + 4) * 68 + d0]);
                mma_tf32(oa[nj], a0, a1, a2, a3, b0, b1);
            }
        }
        __syncthreads();
        if (kt < 6) {
            uint32_t dof = (kt & 1) ? OFF_KV1 : OFF_KV0;
#pragma unroll
            for (int i = 0; i < 4; i++) {
                int id = tid + 512 * i;
                int tok = id >> 4, c4 = id & 15;
                CP16(sb + (dof + tok * 68 + c4 * 4) * 4,
                     Vb + ((kt + 2) * 128 + tok) * 64 + c4 * 4);
            }
            CPC();
        }
    }

    // 4-way kp partial reduction via smem (KV0 region: 4 x 32 x 68)
    {
        float* op = sm + OFF_KV0 + kp * 2176;
        int rb = mh * 16 + g;
#pragma unroll
        for (int nj = 0; nj < 4; nj++) {
            int col = nh * 32 + nj * 8 + 2 * t;
            op[rb * 68 + col]           = oa[nj][0];
            op[rb * 68 + col + 1]       = oa[nj][1];
            op[(rb + 8) * 68 + col]     = oa[nj][2];
            op[(rb + 8) * 68 + col + 1] = oa[nj][3];
        }
    }
    __syncthreads();
#pragma unroll
    for (int e = 0; e < 4; e++) {
        int idx = tid + e * 512;
        int q = idx >> 6, d = idx & 63;
        float val = (sm[OFF_KV0 + q * 68 + d]
                   + sm[OFF_KV0 + 2176 + q * 68 + d]
                   + sm[OFF_KV0 + 2 * 2176 + q * 68 + d]
                   + sm[OFF_KV0 + 3 * 2176 + q * 68 + d]) * sm[OFF_R + q];
        // pre-round for gemm<3> consumption
        g_O[((size_t)(b * NT + q0 + q)) * NDM + h * 64 + d] = roundtf(val);
    }
}

__global__ void finalize_cov_kernel(const float* __restrict__ coverage,
                                    float* __restrict__ outcov)
{
    int i = blockIdx.x * 256 + threadIdx.x;
    if (i < NB * NT) outcov[i] = coverage[i] + g_covacc[i] * (1.0f / NH);
}

// ================= launcher =================
extern "C" void kernel_launch(void* const* d_in, const int* in_sizes, int n_in,
                              void* d_out, int out_size)
{
    const float* query    = (const float*)d_in[0];
    const float* memory   = (const float*)d_in[1];
    const float* coverage = (const float*)d_in[2];
    const float* Wq       = (const float*)d_in[3];
    const float* bq       = (const float*)d_in[4];
    const float* Wk       = (const float*)d_in[5];
    const float* bk       = (const float*)d_in[6];
    const float* Wv       = (const float*)d_in[7];
    const float* bv       = (const float*)d_in[8];
    const float* Wo       = (const float*)d_in[9];
    const float* bo       = (const float*)d_in[10];
    const float* Wcov     = (const float*)d_in[11];
    float* out = (float*)d_out;

    cudaFuncSetAttribute(gemm_mma<0>, cudaFuncAttributeMaxDynamicSharedMemorySize, G_SMEM_BYTES);
    cudaFuncSetAttribute(gemm_mma<1>, cudaFuncAttributeMaxDynamicSharedMemorySize, G_SMEM_BYTES);
    cudaFuncSetAttribute(gemm_mma<2>, cudaFuncAttributeMaxDynamicSharedMemorySize, G_SMEM_BYTES);
    cudaFuncSetAttribute(gemm_mma<3>, cudaFuncAttributeMaxDynamicSharedMemorySize, G_SMEM_BYTES);
    cudaFuncSetAttribute(attn_mma, cudaFuncAttributeMaxDynamicSharedMemorySize, A_SMEM_BYTES);

    zero_covacc_kernel<<<32, 256>>>();

    dim3 gg(NDM / 256, (NB * NT) / 128);   // (4, 64)
    gemm_mma<0><<<gg, 256, G_SMEM_BYTES>>>(query,  Wq, bq, nullptr);
    gemm_mma<1><<<gg, 256, G_SMEM_BYTES>>>(memory, Wk, bk, nullptr);
    gemm_mma<2><<<gg, 256, G_SMEM_BYTES>>>(memory, Wv, bv, nullptr);

    attn_mma<<<dim3(NT / 32, NB * NH), 512, A_SMEM_BYTES>>>(coverage, Wcov);

    gemm_mma<3><<<gg, 256, G_SMEM_BYTES>>>(nullptr, Wo, bo, out);

    finalize_cov_kernel<<<32, 256>>>(coverage, out + (size_t)NB * NT * NDM);
}

// round 8
// speedup vs baseline: 1.7775x; 1.7775x over previous
#include <cuda_runtime.h>
#include <cstdint>

// CoverageAttention GB300 — R7: R4 structure (64x32 warp tile, 2 CTA/SM) +
// fused QKV projection launch + split MMA accumulator chains + tf32 pre-round.
// B=8, Tq=Tk=1024, d_model=1024, H=16, hd=64, SCALE=8.

#define NB   8
#define NH   16
#define NT   1024
#define NDM  1024
#define NHD  64

__device__ float g_Q[NB * NH * NT * NHD];
__device__ float g_K[NB * NH * NT * NHD];
__device__ float g_V[NB * NH * NT * NHD];
__device__ float g_O[NB * NT * NDM];
__device__ float g_covacc[NB * NT];

__global__ void zero_covacc_kernel() {
    int i = blockIdx.x * 256 + threadIdx.x;
    if (i < NB * NT) g_covacc[i] = 0.0f;
}

__device__ __forceinline__ uint32_t smem_u32(const void* p) {
    uint32_t a;
    asm("{ .reg .u64 t; cvta.to.shared.u64 t, %1; cvt.u32.u64 %0, t; }" : "=r"(a) : "l"(p));
    return a;
}
__device__ __forceinline__ uint32_t f2tf32(float x) {
    uint32_t r;
    asm("cvt.rna.tf32.f32 %0, %1;" : "=r"(r) : "f"(x));
    return r;
}
__device__ __forceinline__ float roundtf(float x) {
    return __uint_as_float(f2tf32(x));
}
__device__ __forceinline__ void mma_tf32(float c[4],
                                         uint32_t a0, uint32_t a1, uint32_t a2, uint32_t a3,
                                         uint32_t b0, uint32_t b1) {
    asm volatile(
        "mma.sync.aligned.m16n8k8.row.col.f32.tf32.tf32.f32 "
        "{%0,%1,%2,%3}, {%4,%5,%6,%7}, {%8,%9}, {%0,%1,%2,%3};"
        : "+f"(c[0]), "+f"(c[1]), "+f"(c[2]), "+f"(c[3])
        : "r"(a0), "r"(a1), "r"(a2), "r"(a3), "r"(b0), "r"(b1));
}

#define CP16(dst, src) \
    asm volatile("cp.async.cg.shared.global [%0], [%1], 16;" :: "r"(dst), "l"(src) : "memory")
#define CPC() asm volatile("cp.async.commit_group;" ::: "memory")
#define CPW(n) asm volatile("cp.async.wait_group %0;" :: "n"(n) : "memory")

// ================= shared tf32 GEMM body =================
// C[m,n] = A[m,:]·W[n,:] + bias[n]; CTA 128x128, BK=16, 8 warps (2x4),
// warp 64x32 = 4x4 m16n8k8. Double-buffered smem, register prefetch.
// ROUND_OUT: round result to tf32 before store (for downstream mma consumers).
template <bool HEADED, bool ROUND_OUT>
__device__ __forceinline__ void gemm_body(
    const float* __restrict__ Ap, const float* __restrict__ W,
    const float* __restrict__ bias, float* __restrict__ dst,
    int bm, int bn)
{
    __shared__ uint32_t As[2][128][20];
    __shared__ uint32_t Ws[2][128][20];

    int tid = threadIdx.x;
    int lane = tid & 31;
    int wid = tid >> 5;
    int warp_m = wid & 1;
    int warp_n = wid >> 1;
    int g = lane >> 2;
    int t = lane & 3;

    int lr = tid >> 1;
    int kc = (tid & 1) * 8;
    const float* aP = Ap + (size_t)(bm + lr) * NDM + kc;
    const float* wP = W  + (size_t)(bn + lr) * NDM + kc;

    float c[4][4][4];
#pragma unroll
    for (int mi = 0; mi < 4; mi++)
#pragma unroll
        for (int ni = 0; ni < 4; ni++)
#pragma unroll
            for (int e = 0; e < 4; e++) c[mi][ni][e] = 0.0f;

    float4 ar0 = *(const float4*)(aP + 0);
    float4 ar1 = *(const float4*)(aP + 4);
    float4 wr0 = *(const float4*)(wP + 0);
    float4 wr1 = *(const float4*)(wP + 4);

    {
        uint4 q0 = {f2tf32(ar0.x), f2tf32(ar0.y), f2tf32(ar0.z), f2tf32(ar0.w)};
        uint4 q1 = {f2tf32(ar1.x), f2tf32(ar1.y), f2tf32(ar1.z), f2tf32(ar1.w)};
        *(uint4*)&As[0][lr][kc]     = q0;
        *(uint4*)&As[0][lr][kc + 4] = q1;
        uint4 p0 = {f2tf32(wr0.x), f2tf32(wr0.y), f2tf32(wr0.z), f2tf32(wr0.w)};
        uint4 p1 = {f2tf32(wr1.x), f2tf32(wr1.y), f2tf32(wr1.z), f2tf32(wr1.w)};
        *(uint4*)&Ws[0][lr][kc]     = p0;
        *(uint4*)&Ws[0][lr][kc + 4] = p1;
    }
    __syncthreads();

    for (int kt = 0; kt < 64; kt++) {
        int cur = kt & 1;
        if (kt < 63) {
            const float* aN = aP + (kt + 1) * 16;
            const float* wN = wP + (kt + 1) * 16;
            ar0 = *(const float4*)(aN + 0);
            ar1 = *(const float4*)(aN + 4);
            wr0 = *(const float4*)(wN + 0);
            wr1 = *(const float4*)(wN + 4);
        }

#pragma unroll
        for (int kk = 0; kk < 16; kk += 8) {
            uint32_t af[4][4];
#pragma unroll
            for (int mi = 0; mi < 4; mi++) {
                int r0 = warp_m * 64 + mi * 16 + g;
                af[mi][0] = As[cur][r0][kk + t];
                af[mi][1] = As[cur][r0 + 8][kk + t];
                af[mi][2] = As[cur][r0][kk + t + 4];
                af[mi][3] = As[cur][r0 + 8][kk + t + 4];
            }
            uint32_t bf[4][2];
#pragma unroll
            for (int ni = 0; ni < 4; ni++) {
                int c0 = warp_n * 32 + ni * 8 + g;
                bf[ni][0] = Ws[cur][c0][kk + t];
                bf[ni][1] = Ws[cur][c0][kk + t + 4];
            }
#pragma unroll
            for (int mi = 0; mi < 4; mi++)
#pragma unroll
                for (int ni = 0; ni < 4; ni++)
                    mma_tf32(c[mi][ni], af[mi][0], af[mi][1], af[mi][2], af[mi][3],
                             bf[ni][0], bf[ni][1]);
        }

        if (kt < 63) {
            int nxt = cur ^ 1;
            uint4 q0 = {f2tf32(ar0.x), f2tf32(ar0.y), f2tf32(ar0.z), f2tf32(ar0.w)};
            uint4 q1 = {f2tf32(ar1.x), f2tf32(ar1.y), f2tf32(ar1.z), f2tf32(ar1.w)};
            *(uint4*)&As[nxt][lr][kc]     = q0;
            *(uint4*)&As[nxt][lr][kc + 4] = q1;
            uint4 p0 = {f2tf32(wr0.x), f2tf32(wr0.y), f2tf32(wr0.z), f2tf32(wr0.w)};
            uint4 p1 = {f2tf32(wr1.x), f2tf32(wr1.y), f2tf32(wr1.z), f2tf32(wr1.w)};
            *(uint4*)&Ws[nxt][lr][kc]     = p0;
            *(uint4*)&Ws[nxt][lr][kc + 4] = p1;
            __syncthreads();
        }
    }

#pragma unroll
    for (int mi = 0; mi < 4; mi++) {
#pragma unroll
        for (int ni = 0; ni < 4; ni++) {
            int n0 = bn + warp_n * 32 + ni * 8 + t * 2;
            float b0v = __ldg(bias + n0);
            float b1v = __ldg(bias + n0 + 1);
#pragma unroll
            for (int rh = 0; rh < 2; rh++) {
                int m = bm + warp_m * 64 + mi * 16 + g + rh * 8;
                float v0 = c[mi][ni][rh * 2 + 0] + b0v;
                float v1 = c[mi][ni][rh * 2 + 1] + b1v;
                if (ROUND_OUT) { v0 = roundtf(v0); v1 = roundtf(v1); }
                if (HEADED) {
                    int bb = m >> 10, tok = m & 1023;
                    size_t base = (((size_t)(bb * NH + (n0 >> 6))) * NT + tok) * NHD + (n0 & 63);
                    dst[base] = v0; dst[base + 1] = v1;
                } else {
                    dst[(size_t)m * NDM + n0] = v0;
                    dst[(size_t)m * NDM + n0 + 1] = v1;
                }
            }
        }
    }
}

// fused QKV projections: blockIdx.z = 0(Q)/1(K)/2(V)
__global__ __launch_bounds__(256, 2) void qkv_gemm(
    const float* __restrict__ query, const float* __restrict__ memory,
    const float* __restrict__ Wq, const float* __restrict__ bq,
    const float* __restrict__ Wk, const float* __restrict__ bk,
    const float* __restrict__ Wv, const float* __restrict__ bv)
{
    int z = blockIdx.z;
    const float* A = (z == 0) ? query : memory;
    const float* W = (z == 0) ? Wq : (z == 1) ? Wk : Wv;
    const float* bias = (z == 0) ? bq : (z == 1) ? bk : bv;
    float* dst = (z == 0) ? g_Q : (z == 1) ? g_K : g_V;
    gemm_body<true, true>(A, W, bias, dst, blockIdx.y * 128, blockIdx.x * 128);
}

// output projection: A = g_O, plain fp32 store
__global__ __launch_bounds__(256, 2) void out_gemm(
    const float* __restrict__ Wo, const float* __restrict__ bo,
    float* __restrict__ Cout)
{
    gemm_body<false, false>((const float*)g_O, Wo, bo, Cout,
                            blockIdx.y * 128, blockIdx.x * 128);
}

// ================= attention (mma.sync, 256 threads) =================
#define SROW    1033
#define OFF_S   0                    // 32 x 1033
#define OFF_KV0 33056                // 128 x 68 (buffer 0)
#define OFF_KV1 41760                // 128 x 68 (buffer 1)
#define OFF_QS  50464                // 32 x 68 Q staging
#define OFF_C   52640                // 1024 coverage bias
#define OFF_R   53664                // 32 reciprocals
#define A_SMEM_FLOATS 53696
#define A_SMEM_BYTES  (A_SMEM_FLOATS * 4)   // 214784

__global__ __launch_bounds__(256) void attn_mma(
    const float* __restrict__ coverage, const float* __restrict__ Wcov)
{
    extern __shared__ float sm[];
    uint32_t sb = smem_u32(sm);
    int tid = threadIdx.x;
    int lane = tid & 31, wid = tid >> 5;
    int g = lane >> 2, t = lane & 3;
    int bh = blockIdx.y, b = bh >> 4, h = bh & 15;
    int q0 = blockIdx.x * 32;
    float wcov = Wcov[h];

    const float* Qb = g_Q + (size_t)bh * NT * NHD + (size_t)q0 * NHD;
    const float* Kb = g_K + (size_t)bh * NT * NHD;
    const float* Vb = g_V + (size_t)bh * NT * NHD;

    // ---- prologue: Q + cov + K0, K1 ----
#pragma unroll
    for (int i = 0; i < 2; i++) {
        int id = tid + 256 * i;
        int q = id >> 4, c4 = id & 15;
        CP16(sb + (OFF_QS + q * 68 + c4 * 4) * 4, Qb + q * 64 + c4 * 4);
    }
    CP16(sb + (OFF_C + tid * 4) * 4, coverage + b * NT + tid * 4);
#pragma unroll
    for (int i = 0; i < 8; i++) {
        int id = tid + 256 * i;
        int tok = id >> 4, c4 = id & 15;
        CP16(sb + (OFF_KV0 + tok * 68 + c4 * 4) * 4, Kb + tok * 64 + c4 * 4);
    }
    CPC();
#pragma unroll
    for (int i = 0; i < 8; i++) {
        int id = tid + 256 * i;
        int tok = id >> 4, c4 = id & 15;
        CP16(sb + (OFF_KV1 + tok * 68 + c4 * 4) * 4, Kb + (128 + tok) * 64 + c4 * 4);
    }
    CPC();
    CPW(1);
    __syncthreads();

    for (int i = tid; i < NT; i += 256) sm[OFF_C + i] *= wcov;

    // Q fragments (producer pre-rounded to tf32 — raw bits)
    uint32_t qf[2][8][4];
#pragma unroll
    for (int mi = 0; mi < 2; mi++)
#pragma unroll
        for (int kk = 0; kk < 8; kk++) {
            int base = OFF_QS + (mi * 16 + g) * 68 + kk * 8 + t;
            qf[mi][kk][0] = __float_as_uint(sm[base]);
            qf[mi][kk][1] = __float_as_uint(sm[base + 8 * 68]);
            qf[mi][kk][2] = __float_as_uint(sm[base + 4]);
            qf[mi][kk][3] = __float_as_uint(sm[base + 8 * 68 + 4]);
        }
    __syncthreads();

    // -------- phase 1: S = QK^T/8 + cov; warp owns 16 tokens --------
    // Split accumulators (even/odd kk) to halve MMA dependency-chain depth.
    int tokb = wid * 16;
    for (int kt = 0; kt < 8; kt++) {
        if (kt) {
            if (kt < 7) { CPW(1); } else { CPW(0); }
            __syncthreads();
        }
        const float* Ks = sm + ((kt & 1) ? OFF_KV1 : OFF_KV0);
#pragma unroll
        for (int nj = 0; nj < 2; nj++) {
            float s0e[4] = {0, 0, 0, 0}, s0o[4] = {0, 0, 0, 0};
            float s1e[4] = {0, 0, 0, 0}, s1o[4] = {0, 0, 0, 0};
            const float* kr = Ks + (tokb + nj * 8 + g) * 68 + t;
#pragma unroll
            for (int kk = 0; kk < 8; kk += 2) {
                uint32_t b0 = __float_as_uint(kr[kk * 8]);
                uint32_t b1 = __float_as_uint(kr[kk * 8 + 4]);
                uint32_t d0 = __float_as_uint(kr[kk * 8 + 8]);
                uint32_t d1 = __float_as_uint(kr[kk * 8 + 12]);
                mma_tf32(s0e, qf[0][kk][0], qf[0][kk][1], qf[0][kk][2], qf[0][kk][3], b0, b1);
                mma_tf32(s1e, qf[1][kk][0], qf[1][kk][1], qf[1][kk][2], qf[1][kk][3], b0, b1);
                mma_tf32(s0o, qf[0][kk+1][0], qf[0][kk+1][1], qf[0][kk+1][2], qf[0][kk+1][3], d0, d1);
                mma_tf32(s1o, qf[1][kk+1][0], qf[1][kk+1][1], qf[1][kk+1][2], qf[1][kk+1][3], d0, d1);
            }
            int kgl = kt * 128 + tokb + nj * 8 + 2 * t;
            float cv0 = sm[OFF_C + kgl], cv1 = sm[OFF_C + kgl + 1];
            sm[OFF_S + g * SROW + kgl]            = (s0e[0] + s0o[0]) * 0.125f + cv0;
            sm[OFF_S + g * SROW + kgl + 1]        = (s0e[1] + s0o[1]) * 0.125f + cv1;
            sm[OFF_S + (g + 8) * SROW + kgl]      = (s0e[2] + s0o[2]) * 0.125f + cv0;
            sm[OFF_S + (g + 8) * SROW + kgl + 1]  = (s0e[3] + s0o[3]) * 0.125f + cv1;
            sm[OFF_S + (g + 16) * SROW + kgl]     = (s1e[0] + s1o[0]) * 0.125f + cv0;
            sm[OFF_S + (g + 16) * SROW + kgl + 1] = (s1e[1] + s1o[1]) * 0.125f + cv1;
            sm[OFF_S + (g + 24) * SROW + kgl]     = (s1e[2] + s1o[2]) * 0.125f + cv0;
            sm[OFF_S + (g + 24) * SROW + kgl + 1] = (s1e[3] + s1o[3]) * 0.125f + cv1;
        }
        __syncthreads();
        if (kt < 6) {
            uint32_t dof = (kt & 1) ? OFF_KV1 : OFF_KV0;
#pragma unroll
            for (int i = 0; i < 8; i++) {
                int id = tid + 256 * i;
                int tok = id >> 4, c4 = id & 15;
                CP16(sb + (dof + tok * 68 + c4 * 4) * 4,
                     Kb + ((kt + 2) * 128 + tok) * 64 + c4 * 4);
            }
            CPC();
        }
    }

    // issue V tiles 0,1 (hidden under softmax)
#pragma unroll
    for (int i = 0; i < 8; i++) {
        int id = tid + 256 * i;
        int tok = id >> 4, c4 = id & 15;
        CP16(sb + (OFF_KV0 + tok * 68 + c4 * 4) * 4, Vb + tok * 64 + c4 * 4);
    }
    CPC();
#pragma unroll
    for (int i = 0; i < 8; i++) {
        int id = tid + 256 * i;
        int tok = id >> 4, c4 = id & 15;
        CP16(sb + (OFF_KV1 + tok * 68 + c4 * 4) * 4, Vb + (128 + tok) * 64 + c4 * 4);
    }
    CPC();

    // -------- phase 2: softmax --------
    for (int q = wid; q < 32; q += 8) {
        float* row = &sm[OFF_S + q * SROW];
        float m = -1e30f;
        for (int k = lane; k < NT; k += 32) m = fmaxf(m, row[k]);
#pragma unroll
        for (int o = 16; o > 0; o >>= 1) m = fmaxf(m, __shfl_xor_sync(0xffffffff, m, o));
        float l = 0.0f;
        for (int k = lane; k < NT; k += 32) {
            float e = __expf(row[k] - m);
            row[k] = e;
            l += e;
        }
#pragma unroll
        for (int o = 16; o > 0; o >>= 1) l += __shfl_xor_sync(0xffffffff, l, o);
        if (lane == 0) sm[OFF_R + q] = 1.0f / l;
    }
    __syncthreads();

    // -------- phase 3: coverage column sums --------
    for (int k = tid; k < NT; k += 256) {
        float s = 0.0f;
#pragma unroll 8
        for (int q = 0; q < 32; q++)
            s += sm[OFF_S + q * SROW + k] * sm[OFF_R + q];
        atomicAdd(&g_covacc[b * NT + k], s);
    }

    // -------- phase 4: O = P @ V --------
    int mh = wid & 1, nh = (wid >> 1) & 1, kp = wid >> 2;
    float oa[4][4];
#pragma unroll
    for (int nj = 0; nj < 4; nj++)
#pragma unroll
        for (int e = 0; e < 4; e++) oa[nj][e] = 0.0f;

    for (int kt = 0; kt < 8; kt++) {
        if (kt < 7) { CPW(1); } else { CPW(0); }
        __syncthreads();
        const float* Vs = sm + ((kt & 1) ? OFF_KV1 : OFF_KV0);
#pragma unroll
        for (int ks8 = 0; ks8 < 8; ks8++) {
            int kb = (ks8 * 2 + kp) * 8;
            int ar = OFF_S + (mh * 16 + g) * SROW + kt * 128 + kb + t;
            uint32_t a0 = f2tf32(sm[ar]);
            uint32_t a1 = f2tf32(sm[ar + 8 * SROW]);
            uint32_t a2 = f2tf32(sm[ar + 4]);
            uint32_t a3 = f2tf32(sm[ar + 8 * SROW + 4]);
#pragma unroll
            for (int nj = 0; nj < 4; nj++) {
                int d0 = nh * 32 + nj * 8 + g;
                uint32_t b0 = __float_as_uint(Vs[(kb + t) * 68 + d0]);
                uint32_t b1 = __float_as_uint(Vs[(kb + t + 4) * 68 + d0]);
                mma_tf32(oa[nj], a0, a1, a2, a3, b0, b1);
            }
        }
        __syncthreads();
        if (kt < 6) {
            uint32_t dof = (kt & 1) ? OFF_KV1 : OFF_KV0;
#pragma unroll
            for (int i = 0; i < 8; i++) {
                int id = tid + 256 * i;
                int tok = id >> 4, c4 = id & 15;
                CP16(sb + (dof + tok * 68 + c4 * 4) * 4,
                     Vb + ((kt + 2) * 128 + tok) * 64 + c4 * 4);
            }
            CPC();
        }
    }

    // 2-way kp partial reduction via smem
    {
        float* op = sm + OFF_KV0 + kp * 2176;
        int rb = mh * 16 + g;
#pragma unroll
        for (int nj = 0; nj < 4; nj++) {
            int col = nh * 32 + nj * 8 + 2 * t;
            op[rb * 68 + col]           = oa[nj][0];
            op[rb * 68 + col + 1]       = oa[nj][1];
            op[(rb + 8) * 68 + col]     = oa[nj][2];
            op[(rb + 8) * 68 + col + 1] = oa[nj][3];
        }
    }
    __syncthreads();
#pragma unroll
    for (int e = 0; e < 8; e++) {
        int idx = tid + e * 256;
        int q = idx >> 6, d = idx & 63;
        float val = (sm[OFF_KV0 + q * 68 + d] + sm[OFF_KV0 + 2176 + q * 68 + d])
                    * sm[OFF_R + q];
        g_O[((size_t)(b * NT + q0 + q)) * NDM + h * 64 + d] = val;
    }
}

__global__ void finalize_cov_kernel(const float* __restrict__ coverage,
                                    float* __restrict__ outcov)
{
    int i = blockIdx.x * 256 + threadIdx.x;
    if (i < NB * NT) outcov[i] = coverage[i] + g_covacc[i] * (1.0f / NH);
}

// ================= launcher =================
extern "C" void kernel_launch(void* const* d_in, const int* in_sizes, int n_in,
                              void* d_out, int out_size)
{
    const float* query    = (const float*)d_in[0];
    const float* memory   = (const float*)d_in[1];
    const float* coverage = (const float*)d_in[2];
    const float* Wq       = (const float*)d_in[3];
    const float* bq       = (const float*)d_in[4];
    const float* Wk       = (const float*)d_in[5];
    const float* bk       = (const float*)d_in[6];
    const float* Wv       = (const float*)d_in[7];
    const float* bv       = (const float*)d_in[8];
    const float* Wo       = (const float*)d_in[9];
    const float* bo       = (const float*)d_in[10];
    const float* Wcov     = (const float*)d_in[11];
    float* out = (float*)d_out;

    cudaFuncSetAttribute(attn_mma, cudaFuncAttributeMaxDynamicSharedMemorySize, A_SMEM_BYTES);

    zero_covacc_kernel<<<32, 256>>>();

    qkv_gemm<<<dim3(NDM / 128, (NB * NT) / 128, 3), 256>>>(
        query, memory, Wq, bq, Wk, bk, Wv, bv);

    attn_mma<<<dim3(NT / 32, NB * NH), 256, A_SMEM_BYTES>>>(coverage, Wcov);

    out_gemm<<<dim3(NDM / 128, (NB * NT) / 128), 256>>>(Wo, bo, out);

    finalize_cov_kernel<<<32, 256>>>(coverage, out + (size_t)NB * NT * NDM);
}

// round 11
// speedup vs baseline: 1.9742x; 1.1107x over previous
#include <cuda_runtime.h>
#include <cstdint>

// CoverageAttention GB300 — R9: pre-rounded tf32 everywhere + cp.async 3-stage
// GEMM pipeline (no cvt / no reg-roundtrip in hot loop) + attention V-bank fix.
// B=8, Tq=Tk=1024, d_model=1024, H=16, hd=64, SCALE=8.

#define NB   8
#define NH   16
#define NT   1024
#define NDM  1024
#define NHD  64

__device__ float g_Q[NB * NH * NT * NHD];
__device__ float g_K[NB * NH * NT * NHD];
__device__ float g_V[NB * NH * NT * NHD];
__device__ float g_O[NB * NT * NDM];
__device__ float g_covacc[NB * NT];
__device__ float g_W4[4][NDM * NDM];          // rounded Wq,Wk,Wv,Wo
__device__ float g_X[2][NB * NT * NDM];       // rounded query, memory

__global__ void zero_covacc_kernel() {
    int i = blockIdx.x * 256 + threadIdx.x;
    if (i < NB * NT) g_covacc[i] = 0.0f;
}

__device__ __forceinline__ uint32_t smem_u32(const void* p) {
    uint32_t a;
    asm("{ .reg .u64 t; cvta.to.shared.u64 t, %1; cvt.u32.u64 %0, t; }" : "=r"(a) : "l"(p));
    return a;
}
__device__ __forceinline__ uint32_t f2tf32(float x) {
    uint32_t r;
    asm("cvt.rna.tf32.f32 %0, %1;" : "=r"(r) : "f"(x));
    return r;
}
__device__ __forceinline__ float roundtf(float x) {
    return __uint_as_float(f2tf32(x));
}
__device__ __forceinline__ void mma_tf32(float c[4],
                                         uint32_t a0, uint32_t a1, uint32_t a2, uint32_t a3,
                                         uint32_t b0, uint32_t b1) {
    asm volatile(
        "mma.sync.aligned.m16n8k8.row.col.f32.tf32.tf32.f32 "
        "{%0,%1,%2,%3}, {%4,%5,%6,%7}, {%8,%9}, {%0,%1,%2,%3};"
        : "+f"(c[0]), "+f"(c[1]), "+f"(c[2]), "+f"(c[3])
        : "r"(a0), "r"(a1), "r"(a2), "r"(a3), "r"(b0), "r"(b1));
}

#define CP16(dst, src) \
    asm volatile("cp.async.cg.shared.global [%0], [%1], 16;" :: "r"(dst), "l"(src) : "memory")
#define CPC() asm volatile("cp.async.commit_group;" ::: "memory")
#define CPW(n) asm volatile("cp.async.wait_group %0;" :: "n"(n) : "memory")

// ---------------- pre-round inputs to tf32 ----------------
// weights: 4 x 2^18 float4; activations: 2 x 2^21 float4. total 5242880 float4.
__global__ void round_inputs_kernel(
    const float4* __restrict__ Wq, const float4* __restrict__ Wk,
    const float4* __restrict__ Wv, const float4* __restrict__ Wo,
    const float4* __restrict__ q,  const float4* __restrict__ mem)
{
    int idx = blockIdx.x * 256 + threadIdx.x;
    if (idx >= 5242880) return;
    float4 v;
    float* dst;
    if (idx < 1048576) {
        int wi = idx >> 18;
        int off = idx & 0x3FFFF;
        const float4* src = (wi == 0) ? Wq : (wi == 1) ? Wk : (wi == 2) ? Wv : Wo;
        v = src[off];
        dst = &g_W4[wi][off * 4];
    } else {
        int j = idx - 1048576;
        int xi = j >> 21;
        int off = j & 0x1FFFFF;
        v = (xi == 0) ? q[off] : mem[off];
        dst = &g_X[xi][off * 4];
    }
    float4 r;
    r.x = roundtf(v.x); r.y = roundtf(v.y); r.z = roundtf(v.z); r.w = roundtf(v.w);
    *(float4*)dst = r;
}

// ================= tf32 GEMM, cp.async 3-stage pipeline =================
// C[m,n] = A[m,:]·W[n,:] + bias[n]; A/W pre-rounded tf32 bits.
// CTA 128x128, BK=16, 8 warps (2x4), warp 64x32 = 4x4 m16n8k8.
// dyn smem: As[3][128][20] + Ws[3][128][20] floats = 61440 B.
#define G_SMEM_BYTES 61440

template <bool HEADED, bool ROUND_OUT>
__device__ __forceinline__ void gemm_body(
    const float* __restrict__ Ap, const float* __restrict__ W,
    const float* __restrict__ bias, float* __restrict__ dst,
    int bm, int bn)
{
    extern __shared__ float gsm[];
    float (*As)[128][20] = (float(*)[128][20])(gsm);
    float (*Ws)[128][20] = (float(*)[128][20])(gsm + 3 * 2560);
    uint32_t sbA = smem_u32(&As[0][0][0]);
    uint32_t sbW = smem_u32(&Ws[0][0][0]);

    int tid = threadIdx.x;
    int lane = tid & 31;
    int wid = tid >> 5;
    int warp_m = wid & 1;
    int warp_n = wid >> 1;
    int g = lane >> 2;
    int t = lane & 3;

    int lr = tid >> 1;
    int kc = (tid & 1) * 8;
    const float* aP = Ap + (size_t)(bm + lr) * NDM + kc;
    const float* wP = W  + (size_t)(bn + lr) * NDM + kc;
    uint32_t dA = sbA + (lr * 20 + kc) * 4;
    uint32_t dW = sbW + (lr * 20 + kc) * 4;

    float c[4][4][4];
#pragma unroll
    for (int mi = 0; mi < 4; mi++)
#pragma unroll
        for (int ni = 0; ni < 4; ni++)
#pragma unroll
            for (int e = 0; e < 4; e++) c[mi][ni][e] = 0.0f;

    // prologue: stages 0,1
#pragma unroll
    for (int s = 0; s < 2; s++) {
        CP16(dA + s * 10240, aP + s * 16);
        CP16(dA + s * 10240 + 16, aP + s * 16 + 4);
        CP16(dW + s * 10240, wP + s * 16);
        CP16(dW + s * 10240 + 16, wP + s * 16 + 4);
        CPC();
    }

    for (int kt = 0; kt < 64; kt++) {
        if (kt < 63) { CPW(1); } else { CPW(0); }
        __syncthreads();

        int slot = kt - (kt / 3) * 3;   // kt % 3

        if (kt + 2 < 64) {
            int ns = (kt + 2) - ((kt + 2) / 3) * 3;
            CP16(dA + ns * 10240, aP + (kt + 2) * 16);
            CP16(dA + ns * 10240 + 16, aP + (kt + 2) * 16 + 4);
            CP16(dW + ns * 10240, wP + (kt + 2) * 16);
            CP16(dW + ns * 10240 + 16, wP + (kt + 2) * 16 + 4);
            CPC();
        }

        const float (*Ac)[20] = As[slot];
        const float (*Wc)[20] = Ws[slot];
#pragma unroll
        for (int kk = 0; kk < 16; kk += 8) {
            uint32_t af[4][4];
#pragma unroll
            for (int mi = 0; mi < 4; mi++) {
                int r0 = warp_m * 64 + mi * 16 + g;
                af[mi][0] = __float_as_uint(Ac[r0][kk + t]);
                af[mi][1] = __float_as_uint(Ac[r0 + 8][kk + t]);
                af[mi][2] = __float_as_uint(Ac[r0][kk + t + 4]);
                af[mi][3] = __float_as_uint(Ac[r0 + 8][kk + t + 4]);
            }
            uint32_t bf[4][2];
#pragma unroll
            for (int ni = 0; ni < 4; ni++) {
                int c0 = warp_n * 32 + ni * 8 + g;
                bf[ni][0] = __float_as_uint(Wc[c0][kk + t]);
                bf[ni][1] = __float_as_uint(Wc[c0][kk + t + 4]);
            }
#pragma unroll
            for (int mi = 0; mi < 4; mi++)
#pragma unroll
                for (int ni = 0; ni < 4; ni++)
                    mma_tf32(c[mi][ni], af[mi][0], af[mi][1], af[mi][2], af[mi][3],
                             bf[ni][0], bf[ni][1]);
        }
        __syncthreads();
    }

#pragma unroll
    for (int mi = 0; mi < 4; mi++) {
#pragma unroll
        for (int ni = 0; ni < 4; ni++) {
            int n0 = bn + warp_n * 32 + ni * 8 + t * 2;
            float b0v = __ldg(bias + n0);
            float b1v = __ldg(bias + n0 + 1);
#pragma unroll
            for (int rh = 0; rh < 2; rh++) {
                int m = bm + warp_m * 64 + mi * 16 + g + rh * 8;
                float v0 = c[mi][ni][rh * 2 + 0] + b0v;
                float v1 = c[mi][ni][rh * 2 + 1] + b1v;
                if (ROUND_OUT) { v0 = roundtf(v0); v1 = roundtf(v1); }
                if (HEADED) {
                    int bb = m >> 10, tok = m & 1023;
                    size_t base = (((size_t)(bb * NH + (n0 >> 6))) * NT + tok) * NHD + (n0 & 63);
                    dst[base] = v0; dst[base + 1] = v1;
                } else {
                    dst[(size_t)m * NDM + n0] = v0;
                    dst[(size_t)m * NDM + n0 + 1] = v1;
                }
            }
        }
    }
}

__global__ __launch_bounds__(256, 2) void qkv_gemm(
    const float* __restrict__ bq, const float* __restrict__ bk,
    const float* __restrict__ bv)
{
    int z = blockIdx.z;
    const float* A = (z == 0) ? g_X[0] : g_X[1];
    const float* W = g_W4[z];
    const float* bias = (z == 0) ? bq : (z == 1) ? bk : bv;
    float* dst = (z == 0) ? g_Q : (z == 1) ? g_K : g_V;
    gemm_body<true, true>(A, W, bias, dst, blockIdx.y * 128, blockIdx.x * 128);
}

__global__ __launch_bounds__(256, 2) void out_gemm(
    const float* __restrict__ bo, float* __restrict__ Cout)
{
    gemm_body<false, false>((const float*)g_O, g_W4[3], bo, Cout,
                            blockIdx.y * 128, blockIdx.x * 128);
}

// ================= attention (mma.sync, 256 threads) =================
// K tiles stride 68 (conflict-free phase1); V tiles stride 72 (conflict-free phase4).
#define SROW    1033
#define OFF_S   0                    // 32 x 1033
#define OFF_KV0 33056                // 128 x 72 buffer 0 (K uses 68-stride region)
#define OFF_KV1 42272                // 128 x 72 buffer 1
#define OFF_QS  51488                // 32 x 68 Q staging
#define OFF_C   53664                // 1024 coverage bias
#define OFF_R   54688                // 32 reciprocals
#define A_SMEM_FLOATS 54720
#define A_SMEM_BYTES  (A_SMEM_FLOATS * 4)   // 218880

__global__ __launch_bounds__(256) void attn_mma(
    const float* __restrict__ coverage, const float* __restrict__ Wcov)
{
    extern __shared__ float sm[];
    uint32_t sb = smem_u32(sm);
    int tid = threadIdx.x;
    int lane = tid & 31, wid = tid >> 5;
    int g = lane >> 2, t = lane & 3;
    int bh = blockIdx.y, b = bh >> 4, h = bh & 15;
    int q0 = blockIdx.x * 32;
    float wcov = Wcov[h];

    const float* Qb = g_Q + (size_t)bh * NT * NHD + (size_t)q0 * NHD;
    const float* Kb = g_K + (size_t)bh * NT * NHD;
    const float* Vb = g_V + (size_t)bh * NT * NHD;

    // ---- prologue: Q + cov + K0, K1 ----
#pragma unroll
    for (int i = 0; i < 2; i++) {
        int id = tid + 256 * i;
        int q = id >> 4, c4 = id & 15;
        CP16(sb + (OFF_QS + q * 68 + c4 * 4) * 4, Qb + q * 64 + c4 * 4);
    }
    CP16(sb + (OFF_C + tid * 4) * 4, coverage + b * NT + tid * 4);
#pragma unroll
    for (int i = 0; i < 8; i++) {
        int id = tid + 256 * i;
        int tok = id >> 4, c4 = id & 15;
        CP16(sb + (OFF_KV0 + tok * 68 + c4 * 4) * 4, Kb + tok * 64 + c4 * 4);
    }
    CPC();
#pragma unroll
    for (int i = 0; i < 8; i++) {
        int id = tid + 256 * i;
        int tok = id >> 4, c4 = id & 15;
        CP16(sb + (OFF_KV1 + tok * 68 + c4 * 4) * 4, Kb + (128 + tok) * 64 + c4 * 4);
    }
    CPC();
    CPW(1);
    __syncthreads();

    for (int i = tid; i < NT; i += 256) sm[OFF_C + i] *= wcov;

    // Q fragments (pre-rounded tf32 — raw bits)
    uint32_t qf[2][8][4];
#pragma unroll
    for (int mi = 0; mi < 2; mi++)
#pragma unroll
        for (int kk = 0; kk < 8; kk++) {
            int base = OFF_QS + (mi * 16 + g) * 68 + kk * 8 + t;
            qf[mi][kk][0] = __float_as_uint(sm[base]);
            qf[mi][kk][1] = __float_as_uint(sm[base + 8 * 68]);
            qf[mi][kk][2] = __float_as_uint(sm[base + 4]);
            qf[mi][kk][3] = __float_as_uint(sm[base + 8 * 68 + 4]);
        }
    __syncthreads();

    // -------- phase 1: S = QK^T/8 + cov; warp owns 16 tokens; split chains ----
    int tokb = wid * 16;
    for (int kt = 0; kt < 8; kt++) {
        if (kt) {
            if (kt < 7) { CPW(1); } else { CPW(0); }
            __syncthreads();
        }
        const float* Ks = sm + ((kt & 1) ? OFF_KV1 : OFF_KV0);
#pragma unroll
        for (int nj = 0; nj < 2; nj++) {
            float s0e[4] = {0, 0, 0, 0}, s0o[4] = {0, 0, 0, 0};
            float s1e[4] = {0, 0, 0, 0}, s1o[4] = {0, 0, 0, 0};
            const float* kr = Ks + (tokb + nj * 8 + g) * 68 + t;
#pragma unroll
            for (int kk = 0; kk < 8; kk += 2) {
                uint32_t b0 = __float_as_uint(kr[kk * 8]);
                uint32_t b1 = __float_as_uint(kr[kk * 8 + 4]);
                uint32_t d0 = __float_as_uint(kr[kk * 8 + 8]);
                uint32_t d1 = __float_as_uint(kr[kk * 8 + 12]);
                mma_tf32(s0e, qf[0][kk][0], qf[0][kk][1], qf[0][kk][2], qf[0][kk][3], b0, b1);
                mma_tf32(s1e, qf[1][kk][0], qf[1][kk][1], qf[1][kk][2], qf[1][kk][3], b0, b1);
                mma_tf32(s0o, qf[0][kk+1][0], qf[0][kk+1][1], qf[0][kk+1][2], qf[0][kk+1][3], d0, d1);
                mma_tf32(s1o, qf[1][kk+1][0], qf[1][kk+1][1], qf[1][kk+1][2], qf[1][kk+1][3], d0, d1);
            }
            int kgl = kt * 128 + tokb + nj * 8 + 2 * t;
            float cv0 = sm[OFF_C + kgl], cv1 = sm[OFF_C + kgl + 1];
            sm[OFF_S + g * SROW + kgl]            = (s0e[0] + s0o[0]) * 0.125f + cv0;
            sm[OFF_S + g * SROW + kgl + 1]        = (s0e[1] + s0o[1]) * 0.125f + cv1;
            sm[OFF_S + (g + 8) * SROW + kgl]      = (s0e[2] + s0o[2]) * 0.125f + cv0;
            sm[OFF_S + (g + 8) * SROW + kgl + 1]  = (s0e[3] + s0o[3]) * 0.125f + cv1;
            sm[OFF_S + (g + 16) * SROW + kgl]     = (s1e[0] + s1o[0]) * 0.125f + cv0;
            sm[OFF_S + (g + 16) * SROW + kgl + 1] = (s1e[1] + s1o[1]) * 0.125f + cv1;
            sm[OFF_S + (g + 24) * SROW + kgl]     = (s1e[2] + s1o[2]) * 0.125f + cv0;
            sm[OFF_S + (g + 24) * SROW + kgl + 1] = (s1e[3] + s1o[3]) * 0.125f + cv1;
        }
        __syncthreads();
        if (kt < 6) {
            uint32_t dof = (kt & 1) ? OFF_KV1 : OFF_KV0;
#pragma unroll
            for (int i = 0; i < 8; i++) {
                int id = tid + 256 * i;
                int tok = id >> 4, c4 = id & 15;
                CP16(sb + (dof + tok * 68 + c4 * 4) * 4,
                     Kb + ((kt + 2) * 128 + tok) * 64 + c4 * 4);
            }
            CPC();
        }
    }

    // issue V tiles 0,1 with stride 72 (hidden under softmax)
#pragma unroll
    for (int i = 0; i < 8; i++) {
        int id = tid + 256 * i;
        int tok = id >> 4, c4 = id & 15;
        CP16(sb + (OFF_KV0 + tok * 72 + c4 * 4) * 4, Vb + tok * 64 + c4 * 4);
    }
    CPC();
#pragma unroll
    for (int i = 0; i < 8; i++) {
        int id = tid + 256 * i;
        int tok = id >> 4, c4 = id & 15;
        CP16(sb + (OFF_KV1 + tok * 72 + c4 * 4) * 4, Vb + (128 + tok) * 64 + c4 * 4);
    }
    CPC();

    // -------- phase 2: softmax --------
    for (int q = wid; q < 32; q += 8) {
        float* row = &sm[OFF_S + q * SROW];
        float m = -1e30f;
        for (int k = lane; k < NT; k += 32) m = fmaxf(m, row[k]);
#pragma unroll
        for (int o = 16; o > 0; o >>= 1) m = fmaxf(m, __shfl_xor_sync(0xffffffff, m, o));
        float l = 0.0f;
        for (int k = lane; k < NT; k += 32) {
            float e = __expf(row[k] - m);
            row[k] = e;
            l += e;
        }
#pragma unroll
        for (int o = 16; o > 0; o >>= 1) l += __shfl_xor_sync(0xffffffff, l, o);
        if (lane == 0) sm[OFF_R + q] = 1.0f / l;
    }
    __syncthreads();

    // -------- phase 3: coverage column sums --------
    for (int k = tid; k < NT; k += 256) {
        float s = 0.0f;
#pragma unroll 8
        for (int q = 0; q < 32; q++)
            s += sm[OFF_S + q * SROW + k] * sm[OFF_R + q];
        atomicAdd(&g_covacc[b * NT + k], s);
    }

    // -------- phase 4: O = P @ V --------
    int mh = wid & 1, nh = (wid >> 1) & 1, kp = wid >> 2;
    float oa[4][4];
#pragma unroll
    for (int nj = 0; nj < 4; nj++)
#pragma unroll
        for (int e = 0; e < 4; e++) oa[nj][e] = 0.0f;

    for (int kt = 0; kt < 8; kt++) {
        if (kt < 7) { CPW(1); } else { CPW(0); }
        __syncthreads();
        const float* Vs = sm + ((kt & 1) ? OFF_KV1 : OFF_KV0);
#pragma unroll
        for (int ks8 = 0; ks8 < 8; ks8++) {
            int kb = (ks8 * 2 + kp) * 8;
            int ar = OFF_S + (mh * 16 + g) * SROW + kt * 128 + kb + t;
            uint32_t a0 = f2tf32(sm[ar]);
            uint32_t a1 = f2tf32(sm[ar + 8 * SROW]);
            uint32_t a2 = f2tf32(sm[ar + 4]);
            uint32_t a3 = f2tf32(sm[ar + 8 * SROW + 4]);
#pragma unroll
            for (int nj = 0; nj < 4; nj++) {
                int d0 = nh * 32 + nj * 8 + g;
                uint32_t b0 = __float_as_uint(Vs[(kb + t) * 72 + d0]);
                uint32_t b1 = __float_as_uint(Vs[(kb + t + 4) * 72 + d0]);
                mma_tf32(oa[nj], a0, a1, a2, a3, b0, b1);
            }
        }
        __syncthreads();
        if (kt < 6) {
            uint32_t dof = (kt & 1) ? OFF_KV1 : OFF_KV0;
#pragma unroll
            for (int i = 0; i < 8; i++) {
                int id = tid + 256 * i;
                int tok = id >> 4, c4 = id & 15;
                CP16(sb + (dof + tok * 72 + c4 * 4) * 4,
                     Vb + ((kt + 2) * 128 + tok) * 64 + c4 * 4);
            }
            CPC();
        }
    }

    // 2-way kp partial reduction via smem
    {
        float* op = sm + OFF_KV0 + kp * 2176;
        int rb = mh * 16 + g;
#pragma unroll
        for (int nj = 0; nj < 4; nj++) {
            int col = nh * 32 + nj * 8 + 2 * t;
            op[rb * 68 + col]           = oa[nj][0];
            op[rb * 68 + col + 1]       = oa[nj][1];
            op[(rb + 8) * 68 + col]     = oa[nj][2];
            op[(rb + 8) * 68 + col + 1] = oa[nj][3];
        }
    }
    __syncthreads();
#pragma unroll
    for (int e = 0; e < 8; e++) {
        int idx = tid + e * 256;
        int q = idx >> 6, d = idx & 63;
        float val = (sm[OFF_KV0 + q * 68 + d] + sm[OFF_KV0 + 2176 + q * 68 + d])
                    * sm[OFF_R + q];
        g_O[((size_t)(b * NT + q0 + q)) * NDM + h * 64 + d] = roundtf(val);
    }
}

__global__ void finalize_cov_kernel(const float* __restrict__ coverage,
                                    float* __restrict__ outcov)
{
    int i = blockIdx.x * 256 + threadIdx.x;
    if (i < NB * NT) outcov[i] = coverage[i] + g_covacc[i] * (1.0f / NH);
}

// ================= launcher =================
extern "C" void kernel_launch(void* const* d_in, const int* in_sizes, int n_in,
                              void* d_out, int out_size)
{
    const float* query    = (const float*)d_in[0];
    const float* memory   = (const float*)d_in[1];
    const float* coverage = (const float*)d_in[2];
    const float* Wq       = (const float*)d_in[3];
    const float* bq       = (const float*)d_in[4];
    const float* Wk       = (const float*)d_in[5];
    const float* bk       = (const float*)d_in[6];
    const float* Wv       = (const float*)d_in[7];
    const float* bv       = (const float*)d_in[8];
    const float* Wo       = (const float*)d_in[9];
    const float* bo       = (const float*)d_in[10];
    const float* Wcov     = (const float*)d_in[11];
    float* out = (float*)d_out;

    cudaFuncSetAttribute(qkv_gemm, cudaFuncAttributeMaxDynamicSharedMemorySize, G_SMEM_BYTES);
    cudaFuncSetAttribute(out_gemm, cudaFuncAttributeMaxDynamicSharedMemorySize, G_SMEM_BYTES);
    cudaFuncSetAttribute(attn_mma, cudaFuncAttributeMaxDynamicSharedMemorySize, A_SMEM_BYTES);

    zero_covacc_kernel<<<32, 256>>>();

    round_inputs_kernel<<<(5242880 + 255) / 256, 256>>>(
        (const float4*)Wq, (const float4*)Wk, (const float4*)Wv, (const float4*)Wo,
        (const float4*)query, (const float4*)memory);

    qkv_gemm<<<dim3(NDM / 128, (NB * NT) / 128, 3), 256, G_SMEM_BYTES>>>(bq, bk, bv);

    attn_mma<<<dim3(NT / 32, NB * NH), 256, A_SMEM_BYTES>>>(coverage, Wcov);

    out_gemm<<<dim3(NDM / 128, (NB * NT) / 128), 256, G_SMEM_BYTES>>>(bo, out);

    finalize_cov_kernel<<<32, 256>>>(coverage, out + (size_t)NB * NT * NDM);
}